// round 16
// baseline (speedup 1.0000x reference)
#include <cuda_runtime.h>
#include <cuda_fp16.h>
#include <cuda_bf16.h>
#include <cstdint>

#define NV 2048
#define NE 8192
#define D  128

// ---------------- device scratch (static: no runtime allocation) ----------------
__device__ __align__(16) float g_w[NE];                          // 32 KB
__device__ __align__(16) __half g_A[(size_t)NV * NE];            // 32 MB  fp16(T*w)
__device__ __align__(16) __half g_B[(size_t)NV * NE];            // 32 MB  fp16(T)
__device__ __align__(16) float g_c1[(size_t)2 * NV * NV];        // 32 MB  gemm1 K-half partials
__device__ __align__(16) __nv_bfloat16 g_adjAh[(size_t)NV * NV]; // 8 MB   hi(adjA)
__device__ __align__(16) __nv_bfloat16 g_adjAl[(size_t)NV * NV]; // 8 MB   lo(adjA)
__device__ __align__(16) __nv_bfloat16 g_HWh[(size_t)D * NV];    // 0.5 MB hi(HW^T) [j][k]
__device__ __align__(16) __nv_bfloat16 g_HWl[(size_t)D * NV];    // 0.5 MB lo(HW^T)
__device__ __align__(16) float g_part[(size_t)8 * NV * D];       // 8 MB   gemm2 partials

// ---------------- helpers ----------------
__device__ __forceinline__ void mma_fp16(float* d, const uint32_t* a, const uint32_t* b) {
    asm volatile(
        "mma.sync.aligned.m16n8k16.row.col.f32.f16.f16.f32 "
        "{%0,%1,%2,%3}, {%4,%5,%6,%7}, {%8,%9}, {%0,%1,%2,%3};\n"
        : "+f"(d[0]), "+f"(d[1]), "+f"(d[2]), "+f"(d[3])
        : "r"(a[0]), "r"(a[1]), "r"(a[2]), "r"(a[3]), "r"(b[0]), "r"(b[1]));
}

__device__ __forceinline__ void mma_bf16(float* d, const uint32_t* a, const uint32_t* b) {
    asm volatile(
        "mma.sync.aligned.m16n8k16.row.col.f32.bf16.bf16.f32 "
        "{%0,%1,%2,%3}, {%4,%5,%6,%7}, {%8,%9}, {%0,%1,%2,%3};\n"
        : "+f"(d[0]), "+f"(d[1]), "+f"(d[2]), "+f"(d[3])
        : "r"(a[0]), "r"(a[1]), "r"(a[2]), "r"(a[3]), "r"(b[0]), "r"(b[1]));
}

__device__ __forceinline__ void ldsm4(uint32_t* r, uint32_t saddr) {
    asm volatile("ldmatrix.sync.aligned.m8n8.x4.shared.b16 {%0,%1,%2,%3}, [%4];"
                 : "=r"(r[0]), "=r"(r[1]), "=r"(r[2]), "=r"(r[3]) : "r"(saddr));
}

__device__ __forceinline__ void cp_async16(uint32_t saddr, const void* g) {
    asm volatile("cp.async.cg.shared.global [%0], [%1], 16;\n" :: "r"(saddr), "l"(g));
}
__device__ __forceinline__ void cp_commit() { asm volatile("cp.async.commit_group;\n" ::: "memory"); }
__device__ __forceinline__ void cp_wait1()  { asm volatile("cp.async.wait_group 1;\n" ::: "memory"); }
__device__ __forceinline__ void cp_wait0()  { asm volatile("cp.async.wait_group 0;\n" ::: "memory"); }

__device__ __forceinline__ uint32_t smem_u32(const void* p) {
    uint32_t a;
    asm("{ .reg .u64 t; cvta.to.shared.u64 t, %1; cvt.u32.u64 %0, t; }" : "=r"(a) : "l"(p));
    return a;
}

__device__ __forceinline__ uint32_t pkh(__half a, __half b) {
    return (uint32_t)__half_as_ushort(a) | ((uint32_t)__half_as_ushort(b) << 16);
}
__device__ __forceinline__ uint32_t pkbf(__nv_bfloat16 a, __nv_bfloat16 b) {
    return (uint32_t)__bfloat16_as_ushort(a) | ((uint32_t)__bfloat16_as_ushort(b) << 16);
}
__device__ __forceinline__ void bfsplit(float v, __nv_bfloat16& h, __nv_bfloat16& l) {
    h = __float2bfloat16_rn(v);
    l = __float2bfloat16_rn(v - __bfloat162float(h));
}

// ---------------- kernel 1: w = H_e @ p  (warp per row) ----------------
__global__ void k_w(const float* __restrict__ He, const float* __restrict__ p) {
    int row  = blockIdx.x * 8 + (threadIdx.x >> 5);
    int lane = threadIdx.x & 31;
    const float* r = He + (size_t)row * D;
    float s = 0.f;
#pragma unroll
    for (int j = 0; j < 4; j++) {
        int k = lane + 32 * j;
        s += r[k] * __ldg(p + k);
    }
#pragma unroll
    for (int o = 16; o > 0; o >>= 1) s += __shfl_xor_sync(0xffffffffu, s, o);
    if (lane == 0) g_w[row] = s;
}

// ---------------- kernel 2: A = fp16(T*w), B = fp16(T)  (one read of T) ----------------
__global__ void __launch_bounds__(256)
k_prep(const float* __restrict__ T) {
    const size_t stride = (size_t)gridDim.x * blockDim.x;   // 524288
    size_t c = (size_t)blockIdx.x * blockDim.x + threadIdx.x;
#pragma unroll
    for (int it = 0; it < 8; it++, c += stride) {
        size_t e  = c * 4;
        int col = (int)(e & (size_t)(NE - 1));
        float4 t = *reinterpret_cast<const float4*>(T + e);
        float4 w = *reinterpret_cast<const float4*>(g_w + col);
        __half a0 = __float2half_rn(t.x * w.x), a1 = __float2half_rn(t.y * w.y);
        __half a2 = __float2half_rn(t.z * w.z), a3 = __float2half_rn(t.w * w.w);
        __half b0 = __float2half_rn(t.x), b1 = __float2half_rn(t.y);
        __half b2 = __float2half_rn(t.z), b3 = __float2half_rn(t.w);
        *reinterpret_cast<uint2*>(g_A + e) = make_uint2(pkh(a0, a1), pkh(a2, a3));
        *reinterpret_cast<uint2*>(g_B + e) = make_uint2(pkh(b0, b1), pkh(b2, b3));
    }
}

// ---------------- kernel 3: HW^T (bf16 hi/lo planes) = (H_v @ weight)^T ----------------
__global__ void k_hw(const float* __restrict__ Hv, const float* __restrict__ W) {
    __shared__ float sh[8][D];
    int r0  = blockIdx.x * 8;
    int tid = threadIdx.x;  // 128 (= output column j)
#pragma unroll
    for (int r = 0; r < 8; r++) sh[r][tid] = Hv[(size_t)(r0 + r) * D + tid];
    __syncthreads();
    float acc[8] = {};
    for (int k = 0; k < D; k++) {
        float wk = W[k * D + tid];
#pragma unroll
        for (int r = 0; r < 8; r++) acc[r] += sh[r][k] * wk;
    }
    __nv_bfloat16 h[8], l[8];
#pragma unroll
    for (int r = 0; r < 8; r++) bfsplit(acc[r], h[r], l[r]);
    uint4 ph = make_uint4(pkbf(h[0], h[1]), pkbf(h[2], h[3]), pkbf(h[4], h[5]), pkbf(h[6], h[7]));
    uint4 pl = make_uint4(pkbf(l[0], l[1]), pkbf(l[2], l[3]), pkbf(l[4], l[5]), pkbf(l[6], l[7]));
    *reinterpret_cast<uint4*>(g_HWh + (size_t)tid * NV + r0) = ph;
    *reinterpret_cast<uint4*>(g_HWl + (size_t)tid * NV + r0) = pl;
}

// ---------------- kernel 4: gemm1 partials: 272 CTAs = 136 tiles x 2 K-halves ----
// C_half = fp16(T*w) @ fp16(T)^T over K-half. 256 threads / 8 warps / CTA,
// 2 CTAs per SM (hardware-scheduled anti-phase replaces named-barrier groups).
// 4x2 grid of 32x64 warp tiles, BK=64, 3-stage cp.async ring, 96KB smem.
#define BM 128
#define BK 64
#define TILE_B 16384                       // 128 rows x 128B
#define STAGE_BYTES (2 * TILE_B)           // A + B = 32KB
#define NSTAGE 3
#define SMEM1_BYTES (NSTAGE * STAGE_BYTES) // 98304 per CTA; x2 CTAs = 192KB/SM

__global__ void __launch_bounds__(256, 2)
k_gemm1p() {
    int bx = blockIdx.x;
    int l  = bx >> 1, gk = bx & 1;
    int bm = 0, rem = 16;
    while (l >= rem) { l -= rem; bm++; rem--; }
    int bn = bm + l;

    extern __shared__ float smem[];
    uint32_t sbase = smem_u32(smem);

    int tid  = threadIdx.x;
    int warp = tid >> 5, lane = tid & 31;
    int wm = warp & 3, wn = warp >> 2;
    int gid = lane >> 2, tig = lane & 3;

    const __half* gA = g_A + (size_t)(bm * BM) * NE + gk * (NE / 2);
    const __half* gB = g_B + (size_t)(bn * BM) * NE + gk * (NE / 2);

    float acc[2][8][4];
#pragma unroll
    for (int m = 0; m < 2; m++)
#pragma unroll
        for (int n = 0; n < 8; n++)
#pragma unroll
            for (int q = 0; q < 4; q++) acc[m][n][q] = 0.f;

    const int nkt = (NE / 2) / BK;  // 64

    auto load_stage = [&](int s, int kt) {
        uint32_t base = sbase + (uint32_t)s * STAGE_BYTES;
        int cc = tid & 7;
#pragma unroll
        for (int i = 0; i < 8; i++) {
            int c = i * 256 + tid;
            int operand = c >> 10;
            int row = (c >> 3) & 127;
            uint32_t off = (uint32_t)(operand * TILE_B + row * 128 + cc * 16);
            uint32_t sw  = off ^ ((off >> 3) & 0x70);
            const __half* src = (operand ? gB : gA)
                              + (size_t)row * NE + kt * BK + cc * 8;
            cp_async16(base + sw, src);
        }
        cp_commit();
    };

    load_stage(0, 0);
    load_stage(1, 1);

    uint32_t xmask = (uint32_t)(lane & 7) << 4;
    uint32_t aoff[2], boff[4];
#pragma unroll
    for (int m = 0; m < 2; m++) {
        int rowA = wm * 32 + m * 16 + (lane & 7) + ((lane >> 3) & 1) * 8;
        aoff[m] = (uint32_t)(rowA * 128 + ((lane >> 4) & 1) * 16);
    }
#pragma unroll
    for (int j = 0; j < 4; j++) {
        int rowB = wn * 64 + j * 16 + (lane & 7) + ((lane >> 3) & 1) * 8;
        boff[j] = (uint32_t)(TILE_B + rowB * 128 + ((lane >> 4) & 1) * 16);
    }

    for (int kt = 0; kt < nkt; kt++) {
        if (kt + 1 < nkt) cp_wait1(); else cp_wait0();
        __syncthreads();
        int s = kt % NSTAGE;
        if (kt + 2 < nkt) load_stage((kt + 2) % NSTAGE, kt + 2);

        uint32_t stb = sbase + (uint32_t)s * STAGE_BYTES;

#pragma unroll
        for (int ks = 0; ks < 4; ks++) {
            uint32_t kb = (uint32_t)(ks * 32);
            uint32_t af[2][4], bf[8][2];
#pragma unroll
            for (int m = 0; m < 2; m++)
                ldsm4(af[m], stb + ((aoff[m] + kb) ^ xmask));
#pragma unroll
            for (int j = 0; j < 4; j++) {
                uint32_t r[4];
                ldsm4(r, stb + ((boff[j] + kb) ^ xmask));
                bf[2 * j][0]     = r[0];
                bf[2 * j + 1][0] = r[1];
                bf[2 * j][1]     = r[2];
                bf[2 * j + 1][1] = r[3];
            }
#pragma unroll
            for (int m = 0; m < 2; m++)
#pragma unroll
                for (int n = 0; n < 8; n++) mma_fp16(acc[m][n], af[m], bf[n]);
        }
    }

    // store fp32 partial tile (coalesced float2, proven pattern)
    float* dst = g_c1 + (size_t)gk * NV * NV + (size_t)(bm * BM) * NV + bn * BM;
#pragma unroll
    for (int m = 0; m < 2; m++) {
        int il0 = wm * 32 + m * 16 + gid;
#pragma unroll
        for (int n = 0; n < 8; n++) {
            int jl = wn * 64 + n * 8 + 2 * tig;
#pragma unroll
            for (int qp = 0; qp < 2; qp++) {
                int il = il0 + qp * 8;
                float2 v = make_float2(acc[m][n][qp * 2], acc[m][n][qp * 2 + 1]);
                *reinterpret_cast<float2*>(dst + (size_t)il * NV + jl) = v;
            }
        }
    }
}

// ---------------- kernel 5: fix = sum halves, mask * adj_v, bf16 planes + mirror ----
#define CSTRIDE 132
#define SMEMF_BYTES (128 * CSTRIDE * 4)   // 67584

__global__ void __launch_bounds__(256)
k_fix(const float* __restrict__ adj_v) {
    int l = blockIdx.x, bm = 0, rem = 16;
    while (l >= rem) { l -= rem; bm++; rem--; }
    int bn = bm + l;

    extern __shared__ float cb[];
    int tid = threadIdx.x;
    bool offdiag = (bm != bn);

    const float* c0 = g_c1 + (size_t)(bm * BM) * NV + bn * BM;
    const float* c1 = c0 + (size_t)NV * NV;

    // direct block (bm,bn): i-major, coalesced
#pragma unroll 4
    for (int it = 0; it < 32; it++) {
        int c  = it * 256 + tid;          // 8192 float2 elems
        int i  = c >> 6;
        int j2 = (c & 63) * 2;
        float2 p0 = *reinterpret_cast<const float2*>(c0 + (size_t)i * NV + j2);
        float2 p1 = *reinterpret_cast<const float2*>(c1 + (size_t)i * NV + j2);
        float v0 = p0.x + p1.x, v1 = p0.y + p1.y;
        int ig = bm * BM + i, jg = bn * BM + j2;
        float a0 = ((ig == jg)     ? 1.0f : v0) * adj_v[(size_t)ig * NV + jg];
        float a1 = ((ig == jg + 1) ? 1.0f : v1) * adj_v[(size_t)ig * NV + jg + 1];
        __nv_bfloat16 h0, l0, h1, l1;
        bfsplit(a0, h0, l0);
        bfsplit(a1, h1, l1);
        *reinterpret_cast<uint32_t*>(g_adjAh + (size_t)ig * NV + jg) = pkbf(h0, h1);
        *reinterpret_cast<uint32_t*>(g_adjAl + (size_t)ig * NV + jg) = pkbf(l0, l1);
        if (offdiag) {
            cb[i * CSTRIDE + j2]     = v0;
            cb[i * CSTRIDE + j2 + 1] = v1;
        }
    }

    if (offdiag) {
        __syncthreads();
        // mirror block (bn,bm): j-major, coalesced
#pragma unroll 4
        for (int it = 0; it < 32; it++) {
            int c  = it * 256 + tid;      // 128 j x 64 i-pairs
            int jl = c >> 6;
            int i0 = (c & 63) * 2;
            int j  = bn * BM + jl;
            size_t rowb = (size_t)j * NV + bm * BM;
            float v0 = cb[i0 * CSTRIDE + jl];
            float v1 = cb[(i0 + 1) * CSTRIDE + jl];
            float w0 = v0 * adj_v[rowb + i0];
            float w1 = v1 * adj_v[rowb + i0 + 1];
            __nv_bfloat16 h0, l0, h1, l1;
            bfsplit(w0, h0, l0);
            bfsplit(w1, h1, l1);
            *reinterpret_cast<uint32_t*>(g_adjAh + rowb + i0) = pkbf(h0, h1);
            *reinterpret_cast<uint32_t*>(g_adjAl + rowb + i0) = pkbf(l0, l1);
        }
    }
}

// ---------------- kernel 6: gemm2 partials = adjA @ HW, bf16 hi/lo tensor ----
#define STAGE2B 65536
#define SMEM2_BYTES (3 * STAGE2B)   // 196608

__global__ void __launch_bounds__(256, 1)
k_gemm2p() {
    int mb = blockIdx.x >> 3;   // 0..15
    int kc = blockIdx.x & 7;    // 0..7

    extern __shared__ float sm2[];
    uint32_t sb = smem_u32(sm2);

    int tid  = threadIdx.x;
    int warp = tid >> 5, lane = tid & 31;
    int wm = warp & 3, wn = warp >> 2;
    int gid = lane >> 2, tig = lane & 3;

    float acc[2][8][4];
#pragma unroll
    for (int m = 0; m < 2; m++)
#pragma unroll
        for (int n = 0; n < 8; n++)
#pragma unroll
            for (int q = 0; q < 4; q++) acc[m][n][q] = 0.f;

    const int nkt = 4;   // K-chunk 256 / BK 64

    auto load_stage = [&](int s, int kt) {
        uint32_t base = sb + (uint32_t)s * STAGE2B;
        int cc = tid & 7, r8 = tid >> 3;
        size_t kbase = (size_t)(kc * 256 + kt * 64 + cc * 8);
#pragma unroll
        for (int tile = 0; tile < 4; tile++) {
            const __nv_bfloat16* base_p =
                (tile == 0) ? g_adjAh + (size_t)(mb * 128) * NV :
                (tile == 1) ? g_adjAl + (size_t)(mb * 128) * NV :
                (tile == 2) ? g_HWh : g_HWl;
#pragma unroll
            for (int rr = 0; rr < 4; rr++) {
                int row = rr * 32 + r8;
                uint32_t off = (uint32_t)(tile * 16384 + row * 128 + cc * 16);
                uint32_t sw  = off ^ ((off >> 3) & 0x70);
                cp_async16(base + sw, base_p + (size_t)row * NV + kbase);
            }
        }
        cp_commit();
    };

    load_stage(0, 0);
    load_stage(1, 1);

    uint32_t xmask = (uint32_t)(lane & 7) << 4;
    uint32_t aoff[2][2], boff[4][2];
#pragma unroll
    for (int m = 0; m < 2; m++) {
        int rowA = wm * 32 + m * 16 + (lane & 7) + ((lane >> 3) & 1) * 8;
#pragma unroll
        for (int p = 0; p < 2; p++)
            aoff[m][p] = (uint32_t)(p * 16384 + rowA * 128 + ((lane >> 4) & 1) * 16);
    }
#pragma unroll
    for (int j = 0; j < 4; j++) {
        int rowB = wn * 64 + j * 16 + (lane & 7) + ((lane >> 3) & 1) * 8;
#pragma unroll
        for (int p = 0; p < 2; p++)
            boff[j][p] = (uint32_t)(32768 + p * 16384 + rowB * 128 + ((lane >> 4) & 1) * 16);
    }

    for (int kt = 0; kt < nkt; kt++) {
        if (kt + 1 < nkt) cp_wait1(); else cp_wait0();
        __syncthreads();
        int s = kt % 3;
        if (kt + 2 < nkt) load_stage((kt + 2) % 3, kt + 2);

        uint32_t stb = sb + (uint32_t)s * STAGE2B;

#pragma unroll
        for (int ks = 0; ks < 4; ks++) {
            uint32_t kb = (uint32_t)(ks * 32);
            uint32_t af[2][2][4];
#pragma unroll
            for (int m = 0; m < 2; m++)
#pragma unroll
                for (int p = 0; p < 2; p++)
                    ldsm4(af[m][p], stb + ((aoff[m][p] + kb) ^ xmask));

#pragma unroll
            for (int h = 0; h < 2; h++) {
                uint32_t bh[4][2], bl[4][2];
#pragma unroll
                for (int j = 0; j < 2; j++) {
                    uint32_t rh[4], rl[4];
                    ldsm4(rh, stb + ((boff[2 * h + j][0] + kb) ^ xmask));
                    ldsm4(rl, stb + ((boff[2 * h + j][1] + kb) ^ xmask));
                    bh[2 * j][0] = rh[0]; bh[2 * j + 1][0] = rh[1];
                    bh[2 * j][1] = rh[2]; bh[2 * j + 1][1] = rh[3];
                    bl[2 * j][0] = rl[0]; bl[2 * j + 1][0] = rl[1];
                    bl[2 * j][1] = rl[2]; bl[2 * j + 1][1] = rl[3];
                }
#pragma unroll
                for (int m = 0; m < 2; m++)
#pragma unroll
                    for (int nt = 0; nt < 4; nt++) {
                        int n = 4 * h + nt;
                        mma_bf16(acc[m][n], af[m][0], bh[nt]);  // hi*hi
                        mma_bf16(acc[m][n], af[m][0], bl[nt]);  // hi*lo
                        mma_bf16(acc[m][n], af[m][1], bh[nt]);  // lo*hi
                    }
            }
        }
    }

    float* dst = g_part + (size_t)kc * NV * D + (size_t)(mb * 128) * D;
#pragma unroll
    for (int m = 0; m < 2; m++) {
        int il0 = wm * 32 + m * 16 + gid;
#pragma unroll
        for (int n = 0; n < 8; n++) {
            int jl = wn * 64 + n * 8 + 2 * tig;
#pragma unroll
            for (int qp = 0; qp < 2; qp++) {
                int il = il0 + qp * 8;
                float2 v = make_float2(acc[m][n][qp * 2], acc[m][n][qp * 2 + 1]);
                *reinterpret_cast<float2*>(dst + (size_t)il * D + jl) = v;
            }
        }
    }
}

// ---------------- kernel 7: out = sum(partials) + bias ----------------
__global__ void __launch_bounds__(256)
k_red(const float* __restrict__ bias, float* __restrict__ out) {
    int idx = blockIdx.x * 256 + threadIdx.x;     // 65536 float4s
    size_t e = (size_t)idx * 4;
    int j = (int)(e & (D - 1));
    float4 a = *reinterpret_cast<const float4*>(bias + j);
#pragma unroll
    for (int kc = 0; kc < 8; kc++) {
        float4 p = *reinterpret_cast<const float4*>(g_part + (size_t)kc * NV * D + e);
        a.x += p.x; a.y += p.y; a.z += p.z; a.w += p.w;
    }
    *reinterpret_cast<float4*>(out + e) = a;
}

// ---------------- launch ----------------
extern "C" void kernel_launch(void* const* d_in, const int* in_sizes, int n_in,
                              void* d_out, int out_size) {
    const float* H_v   = (const float*)d_in[0];
    const float* H_e   = (const float*)d_in[1];
    // d_in[2] = adj_e : UNUSED by the reference graph (node_layer branch)
    const float* adj_v = (const float*)d_in[3];
    const float* T     = (const float*)d_in[4];
    const float* W     = (const float*)d_in[5];
    const float* p     = (const float*)d_in[6];
    const float* bias  = (const float*)d_in[7];
    float* out = (float*)d_out;

    k_w<<<NE / 8, 256>>>(H_e, p);
    k_prep<<<2048, 256>>>(T);
    k_hw<<<NV / 8, 128>>>(H_v, W);

    cudaFuncSetAttribute(k_gemm1p, cudaFuncAttributeMaxDynamicSharedMemorySize, SMEM1_BYTES);
    k_gemm1p<<<272, 256, SMEM1_BYTES>>>();

    cudaFuncSetAttribute(k_fix, cudaFuncAttributeMaxDynamicSharedMemorySize, SMEMF_BYTES);
    k_fix<<<136, 256, SMEMF_BYTES>>>(adj_v);

    cudaFuncSetAttribute(k_gemm2p, cudaFuncAttributeMaxDynamicSharedMemorySize, SMEM2_BYTES);
    k_gemm2p<<<128, 256, SMEM2_BYTES>>>();

    k_red<<<256, 256>>>(bias, out);

    // second output: H_e passthrough, concatenated after ret
    if (out_size >= NV * D + NE * D) {
        cudaMemcpyAsync(out + NV * D, H_e, (size_t)NE * D * sizeof(float),
                        cudaMemcpyDeviceToDevice, 0);
    }
}